// round 2
// baseline (speedup 1.0000x reference)
#include <cuda_runtime.h>
#include <math.h>

#define NB   4
#define NPB  4096
#define NN   (NB * NPB)
#define DIM  6
#define KNN  16

// ---------------- scratch (device globals; no allocation allowed) ----------------
__device__ float g_buf1[NN * 256];
__device__ float g_buf2[NN * 256];
__device__ float g_als[NN * 4];
__device__ float g_ald[NN * 4];
__device__ int   g_knn[NN * KNN];

__device__ __forceinline__ float gelu_f(float v) {
    return 0.5f * v * (1.0f + erff(v * 0.70710678118654752f));
}

// =======================================================================
// kNN: per-batch brute force. Block = 256 threads, 64 dst nodes/block.
// 8 sub-threads per node, each thread owns 2 nodes (amortizes smem reads).
// Batch coords (+ squared norm) staged in 128KB dynamic smem, 8 floats/node.
// =======================================================================
#define KNN_SMEM (NPB * 8 * 4)

__global__ void knn_kernel(const float* __restrict__ x, int* __restrict__ knn_out) {
    extern __shared__ float smem[];
    const int batch    = blockIdx.x >> 6;         // 64 blocks per batch
    const int nodeBase = (blockIdx.x & 63) << 6;  // 64 nodes per block
    const int tid = threadIdx.x;

    const float* xb = x + (size_t)batch * NPB * DIM;
    for (int i = tid; i < NPB; i += 256) {
        float v0 = xb[i*6+0], v1 = xb[i*6+1], v2 = xb[i*6+2];
        float v3 = xb[i*6+3], v4 = xb[i*6+4], v5 = xb[i*6+5];
        float s = v0*v0 + v1*v1 + v2*v2 + v3*v3 + v4*v4 + v5*v5;
        float4* row = (float4*)(smem + i*8);
        row[0] = make_float4(v0, v1, v2, v3);
        row[1] = make_float4(v4, v5, s, 0.f);
    }
    __syncthreads();

    const int r = tid & 7;     // sub-thread: candidates j ≡ r (mod 8)
    const int p = tid >> 3;    // 0..31
    int loc[2] = { nodeBase + p, nodeBase + p + 32 };

    float q[2][6], sqi[2];
#pragma unroll
    for (int s = 0; s < 2; ++s) {
        const float4 c0 = *(const float4*)(smem + loc[s]*8);
        const float4 c1 = *(const float4*)(smem + loc[s]*8 + 4);
        q[s][0]=c0.x; q[s][1]=c0.y; q[s][2]=c0.z; q[s][3]=c0.w;
        q[s][4]=c1.x; q[s][5]=c1.y; sqi[s]=c1.z;
    }

    float bd[2][KNN]; int bi[2][KNN];
#pragma unroll
    for (int s = 0; s < 2; ++s)
#pragma unroll
        for (int k = 0; k < KNN; ++k) { bd[s][k] = 3.4e38f; bi[s][k] = 0; }

    for (int j = r; j < NPB; j += 8) {
        const float4 c0 = *(const float4*)(smem + j*8);
        const float4 c1 = *(const float4*)(smem + j*8 + 4);
#pragma unroll
        for (int s = 0; s < 2; ++s) {
            if (j != loc[s]) {
                float dot = q[s][0]*c0.x + q[s][1]*c0.y + q[s][2]*c0.z
                          + q[s][3]*c0.w + q[s][4]*c1.x + q[s][5]*c1.y;
                float d2 = sqi[s] + c1.z - 2.f*dot;   // same formula as reference
                if (d2 < bd[s][KNN-1]) {
                    bd[s][KNN-1] = d2; bi[s][KNN-1] = j;
#pragma unroll
                    for (int k = KNN-1; k > 0; --k) {
                        if (bd[s][k] < bd[s][k-1]) {
                            float td = bd[s][k]; bd[s][k] = bd[s][k-1]; bd[s][k-1] = td;
                            int ti = bi[s][k]; bi[s][k] = bi[s][k-1]; bi[s][k-1] = ti;
                        }
                    }
                }
            }
        }
    }
    __syncthreads();

    // dump sorted per-thread lists into smem scratch (reuses coord buffer)
#pragma unroll
    for (int s = 0; s < 2; ++s) {
        float* dst = smem + (tid*2 + s) * 32;
        int* dsti = (int*)(dst + 16);
#pragma unroll
        for (int k = 0; k < KNN; ++k) { dst[k] = bd[s][k]; dsti[k] = bi[s][k]; }
    }
    __syncthreads();

    if (tid < 64) {
        const int pp = tid & 31, slot = tid >> 5;   // node = nodeBase + tid
        const float* L[8]; const int* I[8]; int ptr[8];
#pragma unroll
        for (int l = 0; l < 8; ++l) {
            const int lid = (pp*8 + l)*2 + slot;
            L[l] = smem + lid*32;
            I[l] = (const int*)(L[l] + 16);
            ptr[l] = 0;
        }
        const int gnode = batch*NPB + nodeBase + tid;
        for (int k = 0; k < KNN; ++k) {
            float bv = 3.4e38f; int bl = 0;
#pragma unroll
            for (int l = 0; l < 8; ++l) {
                const float v = L[l][ptr[l]];
                if (v < bv) { bv = v; bl = l; }
            }
            knn_out[gnode*KNN + k] = batch*NPB + I[bl][ptr[bl]];
            ptr[bl]++;
        }
    }
}

// =======================================================================
// small-K GEMM (K=6): out[n, :] = A[n, :6] @ W[6, N] (+bias) (+addend row)
// thread -> (node, 4 cols)
// =======================================================================
template<int KD>
__global__ void gemm_smallK(const float* __restrict__ A, const float* __restrict__ W,
                            const float* __restrict__ bias, const float* __restrict__ addend,
                            float* __restrict__ out, int N) {
    const int idx = blockIdx.x * blockDim.x + threadIdx.x;
    const int nc = N >> 2;
    const int node = idx / nc;
    const int c = (idx - node*nc) << 2;
    if (node >= NN) return;
    float a[KD];
#pragma unroll
    for (int d = 0; d < KD; ++d) a[d] = A[(size_t)node*KD + d];
    float4 acc = bias ? *(const float4*)(bias + c) : make_float4(0.f,0.f,0.f,0.f);
#pragma unroll
    for (int d = 0; d < KD; ++d) {
        const float4 wv = *(const float4*)(W + d*N + c);
        acc.x += a[d]*wv.x; acc.y += a[d]*wv.y; acc.z += a[d]*wv.z; acc.w += a[d]*wv.w;
    }
    if (addend) {
        const float4 v = *(const float4*)(addend + (size_t)node*N + c);
        acc.x += v.x; acc.y += v.y; acc.z += v.z; acc.w += v.w;
    }
    *(float4*)(out + (size_t)node*N + c) = acc;
}

// =======================================================================
// tiled fp32 GEMM, 128x128 block tile, 8x8 thread tile, BK=8, 256 threads
// register-prefetch double buffering: next tile's global loads issue
// before the compute loop of the current tile.
// =======================================================================
template<bool GELU>
__global__ __launch_bounds__(256)
void gemm_tiled128(const float* __restrict__ A, const float* __restrict__ B,
                   const float* __restrict__ bias, float* __restrict__ C,
                   int M, int N, int K) {
    __shared__ float As[8][128];
    __shared__ float Bs[8][128];
    const int tid = threadIdx.x;
    const int tx = tid & 15, ty = tid >> 4;
    const int rowBase = blockIdx.y * 128, colBase = blockIdx.x * 128;
    float acc[8][8] = {};
    const int lin = tid * 4;
    const int ar = lin >> 3, ak = lin & 7;
    const int bk = lin >> 7, bc = lin & 127;

    const float* Aptr = A + (size_t)(rowBase + ar)*K + ak;
    const float* Bptr = B + (size_t)bk*N + colBase + bc;

    float4 a_next = *(const float4*)Aptr;
    float4 b_next = *(const float4*)Bptr;

    for (int k0 = 0; k0 < K; k0 += 8) {
        // commit prefetched tile to smem
        As[ak+0][ar]=a_next.x; As[ak+1][ar]=a_next.y; As[ak+2][ar]=a_next.z; As[ak+3][ar]=a_next.w;
        *(float4*)&Bs[bk][bc] = b_next;
        __syncthreads();

        // prefetch next tile into registers (overlaps with compute below)
        if (k0 + 8 < K) {
            a_next = *(const float4*)(Aptr + k0 + 8);
            b_next = *(const float4*)(Bptr + (size_t)(k0 + 8)*N);
        }

#pragma unroll
        for (int kk = 0; kk < 8; ++kk) {
            float a_[8], b_[8];
            *(float4*)&a_[0] = *(const float4*)&As[kk][ty*8];
            *(float4*)&a_[4] = *(const float4*)&As[kk][ty*8+4];
            *(float4*)&b_[0] = *(const float4*)&Bs[kk][tx*8];
            *(float4*)&b_[4] = *(const float4*)&Bs[kk][tx*8+4];
#pragma unroll
            for (int i = 0; i < 8; ++i)
#pragma unroll
                for (int j = 0; j < 8; ++j) acc[i][j] += a_[i]*b_[j];
        }
        __syncthreads();
    }
    float bb[8] = {0,0,0,0,0,0,0,0};
    if (bias) {
        *(float4*)&bb[0] = *(const float4*)(bias + colBase + tx*8);
        *(float4*)&bb[4] = *(const float4*)(bias + colBase + tx*8 + 4);
    }
#pragma unroll
    for (int i = 0; i < 8; ++i) {
        float r[8];
#pragma unroll
        for (int j = 0; j < 8; ++j) {
            float v = acc[i][j] + bb[j];
            r[j] = GELU ? gelu_f(v) : v;
        }
        float* cp = C + (size_t)(rowBase + ty*8 + i)*N + colBase + tx*8;
        *(float4*)cp       = *(float4*)&r[0];
        *(float4*)(cp + 4) = *(float4*)&r[4];
    }
}

// =======================================================================
// tiled fp32 GEMM, 64x64 tile (for N=64), 4x4 thread tile, BK=16
// =======================================================================
template<bool GELU>
__global__ __launch_bounds__(256)
void gemm_tiled64(const float* __restrict__ A, const float* __restrict__ B,
                  const float* __restrict__ bias, float* __restrict__ C,
                  int M, int N, int K) {
    __shared__ float As[16][64];
    __shared__ float Bs[16][64];
    const int tid = threadIdx.x;
    const int tx = tid & 15, ty = tid >> 4;
    const int rowBase = blockIdx.y * 64, colBase = blockIdx.x * 64;
    float acc[4][4] = {};
    const int lin = tid * 4;
    const int ar = lin >> 4, ak = lin & 15;
    const int bk = lin >> 6, bc = lin & 63;

    const float* Aptr = A + (size_t)(rowBase + ar)*K + ak;
    const float* Bptr = B + (size_t)bk*N + colBase + bc;
    float4 a_next = *(const float4*)Aptr;
    float4 b_next = *(const float4*)Bptr;

    for (int k0 = 0; k0 < K; k0 += 16) {
        As[ak+0][ar]=a_next.x; As[ak+1][ar]=a_next.y; As[ak+2][ar]=a_next.z; As[ak+3][ar]=a_next.w;
        *(float4*)&Bs[bk][bc] = b_next;
        __syncthreads();

        if (k0 + 16 < K) {
            a_next = *(const float4*)(Aptr + k0 + 16);
            b_next = *(const float4*)(Bptr + (size_t)(k0 + 16)*N);
        }

#pragma unroll
        for (int kk = 0; kk < 16; ++kk) {
            float4 av = *(const float4*)&As[kk][ty*4];
            float4 bv = *(const float4*)&Bs[kk][tx*4];
            float a_[4] = {av.x,av.y,av.z,av.w};
            float b_[4] = {bv.x,bv.y,bv.z,bv.w};
#pragma unroll
            for (int i = 0; i < 4; ++i)
#pragma unroll
                for (int j = 0; j < 4; ++j) acc[i][j] += a_[i]*b_[j];
        }
        __syncthreads();
    }
    float4 bb = bias ? *(const float4*)(bias + colBase + tx*4) : make_float4(0.f,0.f,0.f,0.f);
#pragma unroll
    for (int i = 0; i < 4; ++i) {
        float4 r;
        r.x = acc[i][0]+bb.x; r.y = acc[i][1]+bb.y; r.z = acc[i][2]+bb.z; r.w = acc[i][3]+bb.w;
        if (GELU) { r.x=gelu_f(r.x); r.y=gelu_f(r.y); r.z=gelu_f(r.z); r.w=gelu_f(r.w); }
        *(float4*)(C + (size_t)(rowBase + ty*4 + i)*N + colBase + tx*4) = r;
    }
}

// =======================================================================
// attention logits: als[n,h] = sum_c h[n,h,c]*a_src[h,c] ; ald likewise
// one warp per node, heads reduced sequentially via shfl
// =======================================================================
template<int H, int C>
__global__ void al_kernel(const float* __restrict__ hf, const float* __restrict__ a_src,
                          const float* __restrict__ a_dst, float* __restrict__ als,
                          float* __restrict__ ald) {
    constexpr int F = H * C;
    constexpr int PER = C / 32;
    const int node = blockIdx.x * 8 + (threadIdx.x >> 5);
    const int lane = threadIdx.x & 31;
    if (node >= NN) return;
    const float* hr = hf + (size_t)node * F;
#pragma unroll
    for (int h = 0; h < H; ++h) {
        float vA = 0.f, vD = 0.f;
#pragma unroll
        for (int u = 0; u < PER; ++u) {
            const int c = h*C + lane*PER + u;
            const float hv = hr[c];
            vA += hv * a_src[c];
            vD += hv * a_dst[c];
        }
#pragma unroll
        for (int off = 16; off; off >>= 1) {
            vA += __shfl_xor_sync(0xffffffffu, vA, off);
            vD += __shfl_xor_sync(0xffffffffu, vD, off);
        }
        if (lane == 0) { als[node*H + h] = vA; ald[node*H + h] = vD; }
    }
}

// =======================================================================
// GAT aggregate: fixed 17 incoming edges (16 kNN + self), per-dst softmax,
// weighted gather, + bias, + gelu.  one warp per dst node.
// =======================================================================
template<int H, int C>
__global__ __launch_bounds__(256)
void agg_kernel(const float* __restrict__ hf, const float* __restrict__ als,
                const float* __restrict__ ald, const int* __restrict__ knn,
                const float* __restrict__ bias, float* __restrict__ out) {
    constexpr int F = H * C;
    constexpr int NCHUNK = F / 128;     // 2 for F=256, 1 for F=128
    const int node = blockIdx.x * 8 + (threadIdx.x >> 5);
    const int lane = threadIdx.x & 31;
    if (node >= NN) return;

    int srcs[17];
#pragma unroll
    for (int j = 0; j < 16; ++j) srcs[j] = knn[node*16 + j];
    srcs[16] = node;   // self-loop

    float aldv[H];
#pragma unroll
    for (int h = 0; h < H; ++h) aldv[h] = ald[node*H + h];

    float w[17][H];
    float mx[H];
#pragma unroll
    for (int h = 0; h < H; ++h) mx[h] = -3.4e38f;
#pragma unroll
    for (int j = 0; j < 17; ++j)
#pragma unroll
        for (int h = 0; h < H; ++h) {
            float z = als[srcs[j]*H + h] + aldv[h];
            z = z > 0.f ? z : 0.2f * z;           // leaky relu, slope 0.2
            w[j][h] = z;
            mx[h] = fmaxf(mx[h], z);
        }
    float den[H];
#pragma unroll
    for (int h = 0; h < H; ++h) den[h] = 0.f;
#pragma unroll
    for (int j = 0; j < 17; ++j)
#pragma unroll
        for (int h = 0; h < H; ++h) {
            float p = __expf(w[j][h] - mx[h]);
            w[j][h] = p; den[h] += p;
        }
#pragma unroll
    for (int h = 0; h < H; ++h) den[h] = 1.f / den[h];
#pragma unroll
    for (int j = 0; j < 17; ++j)
#pragma unroll
        for (int h = 0; h < H; ++h) w[j][h] *= den[h];

    float4 acc[NCHUNK];
#pragma unroll
    for (int u = 0; u < NCHUNK; ++u) acc[u] = make_float4(0.f,0.f,0.f,0.f);
#pragma unroll
    for (int j = 0; j < 17; ++j) {
        const float* row = hf + (size_t)srcs[j] * F;
#pragma unroll
        for (int u = 0; u < NCHUNK; ++u) {
            const float4 v = *(const float4*)(row + u*128 + lane*4);
            float al;
            if constexpr (H == 1) al = w[j][0];
            else al = (lane < 16) ? w[j][u*2] : w[j][u*2 + 1];   // head = col/64
            acc[u].x += al*v.x; acc[u].y += al*v.y; acc[u].z += al*v.z; acc[u].w += al*v.w;
        }
    }
    float* o = out + (size_t)node * F;
#pragma unroll
    for (int u = 0; u < NCHUNK; ++u) {
        const float4 bb = *(const float4*)(bias + u*128 + lane*4);
        float4 r;
        r.x = gelu_f(acc[u].x + bb.x);
        r.y = gelu_f(acc[u].y + bb.y);
        r.z = gelu_f(acc[u].z + bb.z);
        r.w = gelu_f(acc[u].w + bb.w);
        *(float4*)(o + u*128 + lane*4) = r;
    }
}

// =======================================================================
// final MLP layer: out[n,o] = z[n,:64] @ m3_W[64,6] + m3_b  (thread per (n,o))
// =======================================================================
__global__ void mlp3_kernel(const float* __restrict__ z, const float* __restrict__ W,
                            const float* __restrict__ b, float* __restrict__ out) {
    const int idx = blockIdx.x * blockDim.x + threadIdx.x;
    if (idx >= NN * 6) return;
    const int node = idx / 6, o = idx - node*6;
    const float* zr = z + (size_t)node * 64;
    float acc = b[o];
#pragma unroll
    for (int k = 0; k < 64; ++k) acc += zr[k] * W[k*6 + o];
    out[idx] = acc;
}

// =======================================================================
extern "C" void kernel_launch(void* const* d_in, const int* in_sizes, int n_in,
                              void* d_out, int out_size) {
    const float* x    = (const float*)d_in[0];
    const float* W1   = (const float*)d_in[1];
    const float* as1  = (const float*)d_in[2];
    const float* ad1  = (const float*)d_in[3];
    const float* b1   = (const float*)d_in[4];
    const float* W2   = (const float*)d_in[5];
    const float* as2  = (const float*)d_in[6];
    const float* ad2  = (const float*)d_in[7];
    const float* b2   = (const float*)d_in[8];
    const float* W3   = (const float*)d_in[9];
    const float* as3  = (const float*)d_in[10];
    const float* ad3  = (const float*)d_in[11];
    const float* b3   = (const float*)d_in[12];
    const float* resW = (const float*)d_in[13];
    const float* resb = (const float*)d_in[14];
    const float* m1W  = (const float*)d_in[15];
    const float* m1b  = (const float*)d_in[16];
    const float* m2W  = (const float*)d_in[17];
    const float* m2b  = (const float*)d_in[18];
    const float* m3W  = (const float*)d_in[19];
    const float* m3b  = (const float*)d_in[20];
    float* out = (float*)d_out;

    float *buf1, *buf2, *als, *ald; int* knn;
    cudaGetSymbolAddress((void**)&buf1, g_buf1);
    cudaGetSymbolAddress((void**)&buf2, g_buf2);
    cudaGetSymbolAddress((void**)&als,  g_als);
    cudaGetSymbolAddress((void**)&ald,  g_ald);
    cudaGetSymbolAddress((void**)&knn,  g_knn);

    cudaFuncSetAttribute(knn_kernel, cudaFuncAttributeMaxDynamicSharedMemorySize, KNN_SMEM);

    // kNN edge structure (16 sources per node; self-loop is implicit)
    knn_kernel<<<256, 256, KNN_SMEM>>>(x, knn);

    // --- GAT layer 1: D=6 -> 256 (4 heads x 64) ---
    gemm_smallK<6><<<4096, 256>>>(x, W1, nullptr, nullptr, buf1, 256);
    al_kernel<4,64><<<2048, 256>>>(buf1, as1, ad1, als, ald);
    agg_kernel<4,64><<<2048, 256>>>(buf1, als, ald, knn, b1, buf2);

    // --- GAT layer 2: 256 -> 256 ---
    gemm_tiled128<false><<<dim3(2,128), 256>>>(buf2, W2, nullptr, buf1, NN, 256, 256);
    al_kernel<4,64><<<2048, 256>>>(buf1, as2, ad2, als, ald);
    agg_kernel<4,64><<<2048, 256>>>(buf1, als, ald, knn, b2, buf2);

    // --- GAT layer 3: 256 -> 128 (1 head) ---
    gemm_tiled128<false><<<dim3(1,128), 256>>>(buf2, W3, nullptr, buf1, NN, 128, 256);
    al_kernel<1,128><<<2048, 256>>>(buf1, as3, ad3, als, ald);
    agg_kernel<1,128><<<2048, 256>>>(buf1, als, ald, knn, b3, buf2);

    // --- residual: buf1 = buf2 + x @ resW + resb ---
    gemm_smallK<6><<<2048, 256>>>(x, resW, resb, buf2, buf1, 128);

    // --- MLP: 128 -> 128 (gelu) -> 64 (gelu) -> 6 ---
    gemm_tiled128<true><<<dim3(1,128), 256>>>(buf1, m1W, m1b, buf2, NN, 128, 128);
    gemm_tiled64<true><<<dim3(1,256), 256>>>(buf2, m2W, m2b, buf1, NN, 64, 128);
    mlp3_kernel<<<384, 256>>>(buf1, m3W, m3b, out);
}

// round 3
// speedup vs baseline: 1.6328x; 1.6328x over previous
#include <cuda_runtime.h>
#include <math.h>

#define NB   4
#define NPB  4096
#define NN   (NB * NPB)
#define DIM  6
#define KNN  16

// ---------------- scratch (device globals; no allocation allowed) ----------------
__device__ float g_buf1[NN * 256];
__device__ float g_buf2[NN * 256];
__device__ float g_als[NN * 4];
__device__ float g_ald[NN * 4];
__device__ int   g_knn[NN * KNN];
__device__ float g_xs[NN * 8];        // packed coords + norm per node

__device__ __forceinline__ float gelu_f(float v) {
    return 0.5f * v * (1.0f + erff(v * 0.70710678118654752f));
}

// =======================================================================
// prep: pack coords + squared norm into 8-float rows (coalesced candidate reads)
// =======================================================================
__global__ void prep_xs(const float* __restrict__ x, float* __restrict__ xs) {
    const int n = blockIdx.x * 256 + threadIdx.x;
    if (n >= NN) return;
    const float v0 = x[n*6+0], v1 = x[n*6+1], v2 = x[n*6+2];
    const float v3 = x[n*6+3], v4 = x[n*6+4], v5 = x[n*6+5];
    const float s = v0*v0 + v1*v1 + v2*v2 + v3*v3 + v4*v4 + v5*v5;
    float4* row = (float4*)(xs + n*8);
    row[0] = make_float4(v0, v1, v2, v3);
    row[1] = make_float4(v4, v5, s, 0.f);
}

// =======================================================================
// kNN v2: 1 thread per (node, r in 0..7). Candidates j ≡ r (mod 8) read via
// coalesced LDG from g_xs (L2-resident). Hot loop only BUFFERS passing
// candidates (d2 < stale threshold) into a private smem slot; the expensive
// sorted-insert chains run only when some lane's buffer fills (~7x total).
// Threshold is stale-conservative => pushed set is a superset of true hits
// => exact top-16 set (all comparisons exact fp32).
// =======================================================================
__global__ __launch_bounds__(256)
void knn_kernel2(const float* __restrict__ xs, int* __restrict__ knn_out) {
    __shared__ float sbufD[256][17];   // 17-pad kills bank conflicts
    __shared__ int   sbufI[256][17];

    const int tid  = threadIdx.x;
    const int gid  = blockIdx.x * 256 + tid;
    const int node = gid >> 3;           // global node id
    const int r    = gid & 7;
    const int batch = node >> 12;        // node / NPB
    const int nloc  = node & (NPB - 1);
    const float* xb = xs + (size_t)batch * NPB * 8;

    // own coords
    const float4 c0 = *(const float4*)(xb + (size_t)nloc * 8);
    const float4 c1 = *(const float4*)(xb + (size_t)nloc * 8 + 4);
    const float q0=c0.x, q1=c0.y, q2=c0.z, q3=c0.w, q4=c1.x, q5=c1.y, sqi=c1.z;

    float ld[16]; int li[16];
#pragma unroll
    for (int k = 0; k < 16; ++k) { ld[k] = 3.4e38f; li[k] = 0; }

    int cnt = 0;
    float thr = 3.4e38f;

    for (int j = r; j < NPB; j += 8) {
        const float4 p0 = *(const float4*)(xb + (size_t)j * 8);
        const float4 p1 = *(const float4*)(xb + (size_t)j * 8 + 4);
        const float dot = q0*p0.x + q1*p0.y + q2*p0.z + q3*p0.w + q4*p1.x + q5*p1.y;
        const float d2 = sqi + p1.z - 2.f*dot;   // identical formula/order to before
        if (d2 < thr && j != nloc) {
            sbufD[tid][cnt] = d2;
            sbufI[tid][cnt] = j;
            cnt++;
        }
        if (__any_sync(0xffffffffu, cnt >= 16)) {
            for (int t = 0; t < cnt; ++t) {
                float v = sbufD[tid][t]; int vi = sbufI[tid][t];
                if (v < ld[15]) {
#pragma unroll
                    for (int k = 0; k < 16; ++k) {
                        const float lk = ld[k]; const int lki = li[k];
                        const bool p = v < lk;
                        const float mn = p ? v : lk;
                        const float mx = p ? lk : v;
                        const int mni = p ? vi : lki;
                        const int mxi = p ? lki : vi;
                        ld[k] = mn; li[k] = mni; v = mx; vi = mxi;
                    }
                }
            }
            cnt = 0;
            thr = ld[15];
        }
    }
    // final flush
    for (int t = 0; t < cnt; ++t) {
        float v = sbufD[tid][t]; int vi = sbufI[tid][t];
        if (v < ld[15]) {
#pragma unroll
            for (int k = 0; k < 16; ++k) {
                const float lk = ld[k]; const int lki = li[k];
                const bool p = v < lk;
                const float mn = p ? v : lk;
                const float mx = p ? lk : v;
                const int mni = p ? vi : lki;
                const int mxi = p ? lki : vi;
                ld[k] = mn; li[k] = mni; v = mx; vi = mxi;
            }
        }
    }

    // publish per-lane sorted lists, then lane r==0 of each node merges the 8
#pragma unroll
    for (int k = 0; k < 16; ++k) { sbufD[tid][k] = ld[k]; sbufI[tid][k] = li[k]; }
    __syncwarp();

    if (r == 0) {
        // own list already in ld/li (sorted). Stream the other 7 lanes' sorted
        // lists; early-break once a list's head can no longer enter top-16.
        for (int l = 1; l < 8; ++l) {
            const int orow = tid + l;
#pragma unroll 1
            for (int k = 0; k < 16; ++k) {
                float v = sbufD[orow][k];
                if (v >= ld[15]) break;        // rest of this sorted list is larger
                int vi = sbufI[orow][k];
#pragma unroll
                for (int kk = 0; kk < 16; ++kk) {
                    const float lk = ld[kk]; const int lki = li[kk];
                    const bool p = v < lk;
                    const float mn = p ? v : lk;
                    const float mx = p ? lk : v;
                    const int mni = p ? vi : lki;
                    const int mxi = p ? lki : vi;
                    ld[kk] = mn; li[kk] = mni; v = mx; vi = mxi;
                }
            }
        }
        const int base = batch * NPB;
#pragma unroll
        for (int k = 0; k < 16; ++k) knn_out[(size_t)node*16 + k] = base + li[k];
    }
}

// =======================================================================
// small-K GEMM (K=6): out[n, :] = A[n, :6] @ W[6, N] (+bias) (+addend row)
// =======================================================================
template<int KD>
__global__ void gemm_smallK(const float* __restrict__ A, const float* __restrict__ W,
                            const float* __restrict__ bias, const float* __restrict__ addend,
                            float* __restrict__ out, int N) {
    const int idx = blockIdx.x * blockDim.x + threadIdx.x;
    const int nc = N >> 2;
    const int node = idx / nc;
    const int c = (idx - node*nc) << 2;
    if (node >= NN) return;
    float a[KD];
#pragma unroll
    for (int d = 0; d < KD; ++d) a[d] = A[(size_t)node*KD + d];
    float4 acc = bias ? *(const float4*)(bias + c) : make_float4(0.f,0.f,0.f,0.f);
#pragma unroll
    for (int d = 0; d < KD; ++d) {
        const float4 wv = *(const float4*)(W + d*N + c);
        acc.x += a[d]*wv.x; acc.y += a[d]*wv.y; acc.z += a[d]*wv.z; acc.w += a[d]*wv.w;
    }
    if (addend) {
        const float4 v = *(const float4*)(addend + (size_t)node*N + c);
        acc.x += v.x; acc.y += v.y; acc.z += v.z; acc.w += v.w;
    }
    *(float4*)(out + (size_t)node*N + c) = acc;
}

// =======================================================================
// tiled fp32 GEMM, 128x128 block tile, 8x8 thread tile, BK=8, 256 threads
// register-prefetch double buffering
// =======================================================================
template<bool GELU>
__global__ __launch_bounds__(256)
void gemm_tiled128(const float* __restrict__ A, const float* __restrict__ B,
                   const float* __restrict__ bias, float* __restrict__ C,
                   int M, int N, int K) {
    __shared__ float As[8][128];
    __shared__ float Bs[8][128];
    const int tid = threadIdx.x;
    const int tx = tid & 15, ty = tid >> 4;
    const int rowBase = blockIdx.y * 128, colBase = blockIdx.x * 128;
    float acc[8][8] = {};
    const int lin = tid * 4;
    const int ar = lin >> 3, ak = lin & 7;
    const int bk = lin >> 7, bc = lin & 127;

    const float* Aptr = A + (size_t)(rowBase + ar)*K + ak;
    const float* Bptr = B + (size_t)bk*N + colBase + bc;

    float4 a_next = *(const float4*)Aptr;
    float4 b_next = *(const float4*)Bptr;

    for (int k0 = 0; k0 < K; k0 += 8) {
        As[ak+0][ar]=a_next.x; As[ak+1][ar]=a_next.y; As[ak+2][ar]=a_next.z; As[ak+3][ar]=a_next.w;
        *(float4*)&Bs[bk][bc] = b_next;
        __syncthreads();

        if (k0 + 8 < K) {
            a_next = *(const float4*)(Aptr + k0 + 8);
            b_next = *(const float4*)(Bptr + (size_t)(k0 + 8)*N);
        }

#pragma unroll
        for (int kk = 0; kk < 8; ++kk) {
            float a_[8], b_[8];
            *(float4*)&a_[0] = *(const float4*)&As[kk][ty*8];
            *(float4*)&a_[4] = *(const float4*)&As[kk][ty*8+4];
            *(float4*)&b_[0] = *(const float4*)&Bs[kk][tx*8];
            *(float4*)&b_[4] = *(const float4*)&Bs[kk][tx*8+4];
#pragma unroll
            for (int i = 0; i < 8; ++i)
#pragma unroll
                for (int j = 0; j < 8; ++j) acc[i][j] += a_[i]*b_[j];
        }
        __syncthreads();
    }
    float bb[8] = {0,0,0,0,0,0,0,0};
    if (bias) {
        *(float4*)&bb[0] = *(const float4*)(bias + colBase + tx*8);
        *(float4*)&bb[4] = *(const float4*)(bias + colBase + tx*8 + 4);
    }
#pragma unroll
    for (int i = 0; i < 8; ++i) {
        float r[8];
#pragma unroll
        for (int j = 0; j < 8; ++j) {
            float v = acc[i][j] + bb[j];
            r[j] = GELU ? gelu_f(v) : v;
        }
        float* cp = C + (size_t)(rowBase + ty*8 + i)*N + colBase + tx*8;
        *(float4*)cp       = *(float4*)&r[0];
        *(float4*)(cp + 4) = *(float4*)&r[4];
    }
}

// =======================================================================
// tiled fp32 GEMM, 64x64 tile (for N=64), 4x4 thread tile, BK=16
// =======================================================================
template<bool GELU>
__global__ __launch_bounds__(256)
void gemm_tiled64(const float* __restrict__ A, const float* __restrict__ B,
                  const float* __restrict__ bias, float* __restrict__ C,
                  int M, int N, int K) {
    __shared__ float As[16][64];
    __shared__ float Bs[16][64];
    const int tid = threadIdx.x;
    const int tx = tid & 15, ty = tid >> 4;
    const int rowBase = blockIdx.y * 64, colBase = blockIdx.x * 64;
    float acc[4][4] = {};
    const int lin = tid * 4;
    const int ar = lin >> 4, ak = lin & 15;
    const int bk = lin >> 6, bc = lin & 63;

    const float* Aptr = A + (size_t)(rowBase + ar)*K + ak;
    const float* Bptr = B + (size_t)bk*N + colBase + bc;
    float4 a_next = *(const float4*)Aptr;
    float4 b_next = *(const float4*)Bptr;

    for (int k0 = 0; k0 < K; k0 += 16) {
        As[ak+0][ar]=a_next.x; As[ak+1][ar]=a_next.y; As[ak+2][ar]=a_next.z; As[ak+3][ar]=a_next.w;
        *(float4*)&Bs[bk][bc] = b_next;
        __syncthreads();

        if (k0 + 16 < K) {
            a_next = *(const float4*)(Aptr + k0 + 16);
            b_next = *(const float4*)(Bptr + (size_t)(k0 + 16)*N);
        }

#pragma unroll
        for (int kk = 0; kk < 16; ++kk) {
            float4 av = *(const float4*)&As[kk][ty*4];
            float4 bv = *(const float4*)&Bs[kk][tx*4];
            float a_[4] = {av.x,av.y,av.z,av.w};
            float b_[4] = {bv.x,bv.y,bv.z,bv.w};
#pragma unroll
            for (int i = 0; i < 4; ++i)
#pragma unroll
                for (int j = 0; j < 4; ++j) acc[i][j] += a_[i]*b_[j];
        }
        __syncthreads();
    }
    float4 bb = bias ? *(const float4*)(bias + colBase + tx*4) : make_float4(0.f,0.f,0.f,0.f);
#pragma unroll
    for (int i = 0; i < 4; ++i) {
        float4 r;
        r.x = acc[i][0]+bb.x; r.y = acc[i][1]+bb.y; r.z = acc[i][2]+bb.z; r.w = acc[i][3]+bb.w;
        if (GELU) { r.x=gelu_f(r.x); r.y=gelu_f(r.y); r.z=gelu_f(r.z); r.w=gelu_f(r.w); }
        *(float4*)(C + (size_t)(rowBase + ty*4 + i)*N + colBase + tx*4) = r;
    }
}

// =======================================================================
// attention logits
// =======================================================================
template<int H, int C>
__global__ void al_kernel(const float* __restrict__ hf, const float* __restrict__ a_src,
                          const float* __restrict__ a_dst, float* __restrict__ als,
                          float* __restrict__ ald) {
    constexpr int F = H * C;
    constexpr int PER = C / 32;
    const int node = blockIdx.x * 8 + (threadIdx.x >> 5);
    const int lane = threadIdx.x & 31;
    if (node >= NN) return;
    const float* hr = hf + (size_t)node * F;
#pragma unroll
    for (int h = 0; h < H; ++h) {
        float vA = 0.f, vD = 0.f;
#pragma unroll
        for (int u = 0; u < PER; ++u) {
            const int c = h*C + lane*PER + u;
            const float hv = hr[c];
            vA += hv * a_src[c];
            vD += hv * a_dst[c];
        }
#pragma unroll
        for (int off = 16; off; off >>= 1) {
            vA += __shfl_xor_sync(0xffffffffu, vA, off);
            vD += __shfl_xor_sync(0xffffffffu, vD, off);
        }
        if (lane == 0) { als[node*H + h] = vA; ald[node*H + h] = vD; }
    }
}

// =======================================================================
// GAT aggregate. H=4 path: each lane only touches heads {hb, hb+2}
// (hb = lane>=16), halving the register-cached softmax state.
// =======================================================================
template<int H, int C>
__global__ __launch_bounds__(256)
void agg_kernel(const float* __restrict__ hf, const float* __restrict__ als,
                const float* __restrict__ ald, const int* __restrict__ knn,
                const float* __restrict__ bias, float* __restrict__ out) {
    constexpr int F = H * C;
    const int node = blockIdx.x * 8 + (threadIdx.x >> 5);
    const int lane = threadIdx.x & 31;
    if (node >= NN) return;

    int srcs[17];
#pragma unroll
    for (int j = 0; j < 16; ++j) srcs[j] = knn[node*16 + j];
    srcs[16] = node;   // self-loop

    if constexpr (H == 4) {
        const int hb = (lane >> 4) & 1;   // 0 or 1
        const float4 adv = *(const float4*)(ald + node*4);
        const float ad0 = hb ? adv.y : adv.x;   // head hb
        const float ad1 = hb ? adv.w : adv.z;   // head hb+2

        float w0[17], w1[17];
        float mx0 = -3.4e38f, mx1 = -3.4e38f;
#pragma unroll
        for (int j = 0; j < 17; ++j) {
            const float4 av = *(const float4*)(als + srcs[j]*4);
            float z0 = (hb ? av.y : av.x) + ad0;
            float z1 = (hb ? av.w : av.z) + ad1;
            z0 = z0 > 0.f ? z0 : 0.2f*z0;
            z1 = z1 > 0.f ? z1 : 0.2f*z1;
            w0[j] = z0; w1[j] = z1;
            mx0 = fmaxf(mx0, z0); mx1 = fmaxf(mx1, z1);
        }
        float den0 = 0.f, den1 = 0.f;
#pragma unroll
        for (int j = 0; j < 17; ++j) {
            const float p0 = __expf(w0[j] - mx0);
            const float p1 = __expf(w1[j] - mx1);
            w0[j] = p0; den0 += p0;
            w1[j] = p1; den1 += p1;
        }
        den0 = 1.f / den0; den1 = 1.f / den1;

        float4 acc0 = make_float4(0.f,0.f,0.f,0.f);
        float4 acc1 = make_float4(0.f,0.f,0.f,0.f);
#pragma unroll
        for (int j = 0; j < 17; ++j) {
            const float* row = hf + (size_t)srcs[j] * F;
            const float a0 = w0[j] * den0;
            const float a1 = w1[j] * den1;
            const float4 v0 = *(const float4*)(row + lane*4);
            const float4 v1 = *(const float4*)(row + 128 + lane*4);
            acc0.x += a0*v0.x; acc0.y += a0*v0.y; acc0.z += a0*v0.z; acc0.w += a0*v0.w;
            acc1.x += a1*v1.x; acc1.y += a1*v1.y; acc1.z += a1*v1.z; acc1.w += a1*v1.w;
        }
        float* o = out + (size_t)node * F;
        const float4 bb0 = *(const float4*)(bias + lane*4);
        const float4 bb1 = *(const float4*)(bias + 128 + lane*4);
        float4 r0, r1;
        r0.x = gelu_f(acc0.x + bb0.x); r0.y = gelu_f(acc0.y + bb0.y);
        r0.z = gelu_f(acc0.z + bb0.z); r0.w = gelu_f(acc0.w + bb0.w);
        r1.x = gelu_f(acc1.x + bb1.x); r1.y = gelu_f(acc1.y + bb1.y);
        r1.z = gelu_f(acc1.z + bb1.z); r1.w = gelu_f(acc1.w + bb1.w);
        *(float4*)(o + lane*4)       = r0;
        *(float4*)(o + 128 + lane*4) = r1;
    } else {
        // H == 1, F == 128
        const float aldv = ald[node];
        float w[17];
        float mx = -3.4e38f;
#pragma unroll
        for (int j = 0; j < 17; ++j) {
            float z = als[srcs[j]] + aldv;
            z = z > 0.f ? z : 0.2f*z;
            w[j] = z; mx = fmaxf(mx, z);
        }
        float den = 0.f;
#pragma unroll
        for (int j = 0; j < 17; ++j) { const float p = __expf(w[j] - mx); w[j] = p; den += p; }
        den = 1.f / den;

        float4 acc = make_float4(0.f,0.f,0.f,0.f);
#pragma unroll
        for (int j = 0; j < 17; ++j) {
            const float* row = hf + (size_t)srcs[j] * F;
            const float a = w[j] * den;
            const float4 v = *(const float4*)(row + lane*4);
            acc.x += a*v.x; acc.y += a*v.y; acc.z += a*v.z; acc.w += a*v.w;
        }
        float* o = out + (size_t)node * F;
        const float4 bb = *(const float4*)(bias + lane*4);
        float4 r;
        r.x = gelu_f(acc.x + bb.x); r.y = gelu_f(acc.y + bb.y);
        r.z = gelu_f(acc.z + bb.z); r.w = gelu_f(acc.w + bb.w);
        *(float4*)(o + lane*4) = r;
    }
}

// =======================================================================
// final MLP layer: out[n,o] = z[n,:64] @ m3_W[64,6] + m3_b
// =======================================================================
__global__ void mlp3_kernel(const float* __restrict__ z, const float* __restrict__ W,
                            const float* __restrict__ b, float* __restrict__ out) {
    const int idx = blockIdx.x * blockDim.x + threadIdx.x;
    if (idx >= NN * 6) return;
    const int node = idx / 6, o = idx - node*6;
    const float* zr = z + (size_t)node * 64;
    float acc = b[o];
#pragma unroll
    for (int k = 0; k < 64; ++k) acc += zr[k] * W[k*6 + o];
    out[idx] = acc;
}

// =======================================================================
extern "C" void kernel_launch(void* const* d_in, const int* in_sizes, int n_in,
                              void* d_out, int out_size) {
    const float* x    = (const float*)d_in[0];
    const float* W1   = (const float*)d_in[1];
    const float* as1  = (const float*)d_in[2];
    const float* ad1  = (const float*)d_in[3];
    const float* b1   = (const float*)d_in[4];
    const float* W2   = (const float*)d_in[5];
    const float* as2  = (const float*)d_in[6];
    const float* ad2  = (const float*)d_in[7];
    const float* b2   = (const float*)d_in[8];
    const float* W3   = (const float*)d_in[9];
    const float* as3  = (const float*)d_in[10];
    const float* ad3  = (const float*)d_in[11];
    const float* b3   = (const float*)d_in[12];
    const float* resW = (const float*)d_in[13];
    const float* resb = (const float*)d_in[14];
    const float* m1W  = (const float*)d_in[15];
    const float* m1b  = (const float*)d_in[16];
    const float* m2W  = (const float*)d_in[17];
    const float* m2b  = (const float*)d_in[18];
    const float* m3W  = (const float*)d_in[19];
    const float* m3b  = (const float*)d_in[20];
    float* out = (float*)d_out;

    float *buf1, *buf2, *als, *ald, *xs; int* knn;
    cudaGetSymbolAddress((void**)&buf1, g_buf1);
    cudaGetSymbolAddress((void**)&buf2, g_buf2);
    cudaGetSymbolAddress((void**)&als,  g_als);
    cudaGetSymbolAddress((void**)&ald,  g_ald);
    cudaGetSymbolAddress((void**)&knn,  g_knn);
    cudaGetSymbolAddress((void**)&xs,   g_xs);

    // kNN edge structure (16 sources per node; self-loop handled in agg)
    prep_xs<<<64, 256>>>(x, xs);
    knn_kernel2<<<512, 256>>>(xs, knn);

    // --- GAT layer 1: D=6 -> 256 (4 heads x 64) ---
    gemm_smallK<6><<<4096, 256>>>(x, W1, nullptr, nullptr, buf1, 256);
    al_kernel<4,64><<<2048, 256>>>(buf1, as1, ad1, als, ald);
    agg_kernel<4,64><<<2048, 256>>>(buf1, als, ald, knn, b1, buf2);

    // --- GAT layer 2: 256 -> 256 ---
    gemm_tiled128<false><<<dim3(2,128), 256>>>(buf2, W2, nullptr, buf1, NN, 256, 256);
    al_kernel<4,64><<<2048, 256>>>(buf1, as2, ad2, als, ald);
    agg_kernel<4,64><<<2048, 256>>>(buf1, als, ald, knn, b2, buf2);

    // --- GAT layer 3: 256 -> 128 (1 head) ---
    gemm_tiled128<false><<<dim3(1,128), 256>>>(buf2, W3, nullptr, buf1, NN, 128, 256);
    al_kernel<1,128><<<2048, 256>>>(buf1, as3, ad3, als, ald);
    agg_kernel<1,128><<<2048, 256>>>(buf1, als, ald, knn, b3, buf2);

    // --- residual: buf1 = buf2 + x @ resW + resb ---
    gemm_smallK<6><<<2048, 256>>>(x, resW, resb, buf2, buf1, 128);

    // --- MLP: 128 -> 128 (gelu) -> 64 (gelu) -> 6 ---
    gemm_tiled128<true><<<dim3(1,128), 256>>>(buf1, m1W, m1b, buf2, NN, 128, 128);
    gemm_tiled64<true><<<dim3(1,256), 256>>>(buf2, m2W, m2b, buf1, NN, 64, 128);
    mlp3_kernel<<<384, 256>>>(buf1, m3W, m3b, out);
}

// round 4
// speedup vs baseline: 1.6848x; 1.0318x over previous
#include <cuda_runtime.h>
#include <math.h>

#define NB   4
#define NPB  4096
#define NN   (NB * NPB)
#define DIM  6
#define KNN  16

// ---------------- scratch (device globals; no allocation allowed) ----------------
__device__ float g_buf1[NN * 256];
__device__ float g_buf2[NN * 256];
__device__ float g_als[NN * 4];
__device__ float g_ald[NN * 4];
__device__ int   g_knn[NN * KNN];
__device__ float g_xs[NN * 8];        // packed coords + norm per node

__device__ __forceinline__ float gelu_f(float v) {
    return 0.5f * v * (1.0f + erff(v * 0.70710678118654752f));
}

__device__ __forceinline__ float to_tf32(float x) {
    float r;
    asm("cvt.rna.tf32.f32 %0, %1;" : "=f"(r) : "f"(x));
    return r;
}

__device__ __forceinline__ void mma_tf32(float* d, const float* a, const float* b) {
    asm volatile(
        "mma.sync.aligned.m16n8k8.row.col.f32.tf32.tf32.f32 "
        "{%0,%1,%2,%3}, {%4,%5,%6,%7}, {%8,%9}, {%0,%1,%2,%3};"
        : "+f"(d[0]), "+f"(d[1]), "+f"(d[2]), "+f"(d[3])
        : "r"(__float_as_uint(a[0])), "r"(__float_as_uint(a[1])),
          "r"(__float_as_uint(a[2])), "r"(__float_as_uint(a[3])),
          "r"(__float_as_uint(b[0])), "r"(__float_as_uint(b[1])));
}

// =======================================================================
// prep: pack coords + squared norm into 8-float rows
// =======================================================================
__global__ void prep_xs(const float* __restrict__ x, float* __restrict__ xs) {
    const int n = blockIdx.x * 256 + threadIdx.x;
    if (n >= NN) return;
    const float v0 = x[n*6+0], v1 = x[n*6+1], v2 = x[n*6+2];
    const float v3 = x[n*6+3], v4 = x[n*6+4], v5 = x[n*6+5];
    const float s = v0*v0 + v1*v1 + v2*v2 + v3*v3 + v4*v4 + v5*v5;
    float4* row = (float4*)(xs + n*8);
    row[0] = make_float4(v0, v1, v2, v3);
    row[1] = make_float4(v4, v5, s, 0.f);
}

// =======================================================================
// kNN v2 (unchanged from R3 — exact selection via conservative threshold)
// =======================================================================
__global__ __launch_bounds__(256)
void knn_kernel2(const float* __restrict__ xs, int* __restrict__ knn_out) {
    __shared__ float sbufD[256][17];
    __shared__ int   sbufI[256][17];

    const int tid  = threadIdx.x;
    const int gid  = blockIdx.x * 256 + tid;
    const int node = gid >> 3;
    const int r    = gid & 7;
    const int batch = node >> 12;
    const int nloc  = node & (NPB - 1);
    const float* xb = xs + (size_t)batch * NPB * 8;

    const float4 c0 = *(const float4*)(xb + (size_t)nloc * 8);
    const float4 c1 = *(const float4*)(xb + (size_t)nloc * 8 + 4);
    const float q0=c0.x, q1=c0.y, q2=c0.z, q3=c0.w, q4=c1.x, q5=c1.y, sqi=c1.z;

    float ld[16]; int li[16];
#pragma unroll
    for (int k = 0; k < 16; ++k) { ld[k] = 3.4e38f; li[k] = 0; }

    int cnt = 0;
    float thr = 3.4e38f;

    for (int j = r; j < NPB; j += 8) {
        const float4 p0 = *(const float4*)(xb + (size_t)j * 8);
        const float4 p1 = *(const float4*)(xb + (size_t)j * 8 + 4);
        const float dot = q0*p0.x + q1*p0.y + q2*p0.z + q3*p0.w + q4*p1.x + q5*p1.y;
        const float d2 = sqi + p1.z - 2.f*dot;
        if (d2 < thr && j != nloc) {
            sbufD[tid][cnt] = d2;
            sbufI[tid][cnt] = j;
            cnt++;
        }
        if (__any_sync(0xffffffffu, cnt >= 16)) {
            for (int t = 0; t < cnt; ++t) {
                float v = sbufD[tid][t]; int vi = sbufI[tid][t];
                if (v < ld[15]) {
#pragma unroll
                    for (int k = 0; k < 16; ++k) {
                        const float lk = ld[k]; const int lki = li[k];
                        const bool p = v < lk;
                        const float mn = p ? v : lk;
                        const float mx = p ? lk : v;
                        const int mni = p ? vi : lki;
                        const int mxi = p ? lki : vi;
                        ld[k] = mn; li[k] = mni; v = mx; vi = mxi;
                    }
                }
            }
            cnt = 0;
            thr = ld[15];
        }
    }
    for (int t = 0; t < cnt; ++t) {
        float v = sbufD[tid][t]; int vi = sbufI[tid][t];
        if (v < ld[15]) {
#pragma unroll
            for (int k = 0; k < 16; ++k) {
                const float lk = ld[k]; const int lki = li[k];
                const bool p = v < lk;
                const float mn = p ? v : lk;
                const float mx = p ? lk : v;
                const int mni = p ? vi : lki;
                const int mxi = p ? lki : vi;
                ld[k] = mn; li[k] = mni; v = mx; vi = mxi;
            }
        }
    }

#pragma unroll
    for (int k = 0; k < 16; ++k) { sbufD[tid][k] = ld[k]; sbufI[tid][k] = li[k]; }
    __syncwarp();

    if (r == 0) {
        for (int l = 1; l < 8; ++l) {
            const int orow = tid + l;
#pragma unroll 1
            for (int k = 0; k < 16; ++k) {
                float v = sbufD[orow][k];
                if (v >= ld[15]) break;
                int vi = sbufI[orow][k];
#pragma unroll
                for (int kk = 0; kk < 16; ++kk) {
                    const float lk = ld[kk]; const int lki = li[kk];
                    const bool p = v < lk;
                    const float mn = p ? v : lk;
                    const float mx = p ? lk : v;
                    const int mni = p ? vi : lki;
                    const int mxi = p ? lki : vi;
                    ld[kk] = mn; li[kk] = mni; v = mx; vi = mxi;
                }
            }
        }
        const int base = batch * NPB;
#pragma unroll
        for (int k = 0; k < 16; ++k) knn_out[(size_t)node*16 + k] = base + li[k];
    }
}

// =======================================================================
// small-K GEMM (K=6)
// =======================================================================
template<int KD>
__global__ void gemm_smallK(const float* __restrict__ A, const float* __restrict__ W,
                            const float* __restrict__ bias, const float* __restrict__ addend,
                            float* __restrict__ out, int N) {
    const int idx = blockIdx.x * blockDim.x + threadIdx.x;
    const int nc = N >> 2;
    const int node = idx / nc;
    const int c = (idx - node*nc) << 2;
    if (node >= NN) return;
    float a[KD];
#pragma unroll
    for (int d = 0; d < KD; ++d) a[d] = A[(size_t)node*KD + d];
    float4 acc = bias ? *(const float4*)(bias + c) : make_float4(0.f,0.f,0.f,0.f);
#pragma unroll
    for (int d = 0; d < KD; ++d) {
        const float4 wv = *(const float4*)(W + d*N + c);
        acc.x += a[d]*wv.x; acc.y += a[d]*wv.y; acc.z += a[d]*wv.z; acc.w += a[d]*wv.w;
    }
    if (addend) {
        const float4 v = *(const float4*)(addend + (size_t)node*N + c);
        acc.x += v.x; acc.y += v.y; acc.z += v.z; acc.w += v.w;
    }
    *(float4*)(out + (size_t)node*N + c) = acc;
}

// =======================================================================
// tf32 tensor-core GEMM, 3-term split (hi*hi + lo*hi + hi*lo) for fp32-grade
// accuracy. Block tile 128x128, 8 warps (2x4), warp tile 64x32, BK=16.
// A smem [m][k] pad 20 (conflict-free frag loads), B smem [k][n] pad 136.
// =======================================================================
#define APAD 20
#define BPAD 136

template<bool GELU>
__global__ __launch_bounds__(256, 2)
void gemm_tf32(const float* __restrict__ A, const float* __restrict__ B,
               const float* __restrict__ bias, float* __restrict__ C,
               int M, int N, int K) {
    __shared__ float Ah[128][APAD], Al[128][APAD];
    __shared__ float Bh[16][BPAD],  Bl[16][BPAD];

    const int tid  = threadIdx.x;
    const int w    = tid >> 5, lane = tid & 31;
    const int gp   = lane >> 2, tg = lane & 3;
    const int wm   = (w & 1) * 64, wn = (w >> 1) * 32;
    const int rowBase = blockIdx.y * 128, colBase = blockIdx.x * 128;

    float acc[4][4][4];
#pragma unroll
    for (int i = 0; i < 4; ++i)
#pragma unroll
        for (int j = 0; j < 4; ++j)
#pragma unroll
            for (int t = 0; t < 4; ++t) acc[i][j][t] = 0.f;

    const int ar = tid >> 1, ak = (tid & 1) * 8;     // A: 8 consecutive k
    const int bk = tid >> 4, bc = (tid & 15) * 8;    // B: 8 consecutive n

    const float* Aptr = A + (size_t)(rowBase + ar) * K + ak;
    const float* Bptr = B + (size_t)bk * N + colBase + bc;

    float4 an0 = *(const float4*)(Aptr);
    float4 an1 = *(const float4*)(Aptr + 4);
    float4 bn0 = *(const float4*)(Bptr);
    float4 bn1 = *(const float4*)(Bptr + 4);

    for (int k0 = 0; k0 < K; k0 += 16) {
        // convert + split + commit to smem
        {
            float va[8] = {an0.x, an0.y, an0.z, an0.w, an1.x, an1.y, an1.z, an1.w};
            float vb[8] = {bn0.x, bn0.y, bn0.z, bn0.w, bn1.x, bn1.y, bn1.z, bn1.w};
            float ah[8], alo[8], bh[8], blo[8];
#pragma unroll
            for (int i = 0; i < 8; ++i) {
                ah[i]  = to_tf32(va[i]);  alo[i] = to_tf32(va[i] - ah[i]);
                bh[i]  = to_tf32(vb[i]);  blo[i] = to_tf32(vb[i] - bh[i]);
            }
            *(float4*)&Ah[ar][ak]     = *(float4*)&ah[0];
            *(float4*)&Ah[ar][ak+4]   = *(float4*)&ah[4];
            *(float4*)&Al[ar][ak]     = *(float4*)&alo[0];
            *(float4*)&Al[ar][ak+4]   = *(float4*)&alo[4];
            *(float4*)&Bh[bk][bc]     = *(float4*)&bh[0];
            *(float4*)&Bh[bk][bc+4]   = *(float4*)&bh[4];
            *(float4*)&Bl[bk][bc]     = *(float4*)&blo[0];
            *(float4*)&Bl[bk][bc+4]   = *(float4*)&blo[4];
        }
        __syncthreads();

        if (k0 + 16 < K) {
            an0 = *(const float4*)(Aptr + k0 + 16);
            an1 = *(const float4*)(Aptr + k0 + 20);
            bn0 = *(const float4*)(Bptr + (size_t)(k0 + 16) * N);
            bn1 = *(const float4*)(Bptr + (size_t)(k0 + 16) * N + 4);
        }

#pragma unroll
        for (int s = 0; s < 16; s += 8) {
            float a_h[4][4], a_l[4][4];
#pragma unroll
            for (int mt = 0; mt < 4; ++mt) {
                const int m = wm + mt*16 + gp;
                a_h[mt][0] = Ah[m][s+tg];     a_h[mt][1] = Ah[m+8][s+tg];
                a_h[mt][2] = Ah[m][s+tg+4];   a_h[mt][3] = Ah[m+8][s+tg+4];
                a_l[mt][0] = Al[m][s+tg];     a_l[mt][1] = Al[m+8][s+tg];
                a_l[mt][2] = Al[m][s+tg+4];   a_l[mt][3] = Al[m+8][s+tg+4];
            }
#pragma unroll
            for (int nt = 0; nt < 4; ++nt) {
                const int n = wn + nt*8 + gp;
                float b_h[2], b_l[2];
                b_h[0] = Bh[s+tg][n];   b_h[1] = Bh[s+tg+4][n];
                b_l[0] = Bl[s+tg][n];   b_l[1] = Bl[s+tg+4][n];
#pragma unroll
                for (int mt = 0; mt < 4; ++mt) {
                    mma_tf32(acc[mt][nt], a_h[mt], b_h);
                    mma_tf32(acc[mt][nt], a_l[mt], b_h);
                    mma_tf32(acc[mt][nt], a_h[mt], b_l);
                }
            }
        }
        __syncthreads();
    }

    // epilogue: c0,c1 -> (row, 2tg / 2tg+1); c2,c3 -> (row+8, ...)
#pragma unroll
    for (int mt = 0; mt < 4; ++mt) {
        const int row0 = rowBase + wm + mt*16 + gp;
#pragma unroll
        for (int nt = 0; nt < 4; ++nt) {
            const int col = colBase + wn + nt*8 + tg*2;
            float b0 = 0.f, b1 = 0.f;
            if (bias) { b0 = bias[col]; b1 = bias[col+1]; }
            float v0 = acc[mt][nt][0] + b0;
            float v1 = acc[mt][nt][1] + b1;
            float v2 = acc[mt][nt][2] + b0;
            float v3 = acc[mt][nt][3] + b1;
            if (GELU) { v0 = gelu_f(v0); v1 = gelu_f(v1); v2 = gelu_f(v2); v3 = gelu_f(v3); }
            *(float2*)(C + (size_t)row0 * N + col)       = make_float2(v0, v1);
            *(float2*)(C + (size_t)(row0+8) * N + col)   = make_float2(v2, v3);
        }
    }
}

// =======================================================================
// tiled fp32 GEMM, 64x64 tile (m2), 4x4 thread tile, BK=16
// =======================================================================
template<bool GELU>
__global__ __launch_bounds__(256)
void gemm_tiled64(const float* __restrict__ A, const float* __restrict__ B,
                  const float* __restrict__ bias, float* __restrict__ C,
                  int M, int N, int K) {
    __shared__ float As[16][64];
    __shared__ float Bs[16][64];
    const int tid = threadIdx.x;
    const int tx = tid & 15, ty = tid >> 4;
    const int rowBase = blockIdx.y * 64, colBase = blockIdx.x * 64;
    float acc[4][4] = {};
    const int lin = tid * 4;
    const int ar = lin >> 4, ak = lin & 15;
    const int bk = lin >> 6, bc = lin & 63;

    const float* Aptr = A + (size_t)(rowBase + ar)*K + ak;
    const float* Bptr = B + (size_t)bk*N + colBase + bc;
    float4 a_next = *(const float4*)Aptr;
    float4 b_next = *(const float4*)Bptr;

    for (int k0 = 0; k0 < K; k0 += 16) {
        As[ak+0][ar]=a_next.x; As[ak+1][ar]=a_next.y; As[ak+2][ar]=a_next.z; As[ak+3][ar]=a_next.w;
        *(float4*)&Bs[bk][bc] = b_next;
        __syncthreads();

        if (k0 + 16 < K) {
            a_next = *(const float4*)(Aptr + k0 + 16);
            b_next = *(const float4*)(Bptr + (size_t)(k0 + 16)*N);
        }

#pragma unroll
        for (int kk = 0; kk < 16; ++kk) {
            float4 av = *(const float4*)&As[kk][ty*4];
            float4 bv = *(const float4*)&Bs[kk][tx*4];
            float a_[4] = {av.x,av.y,av.z,av.w};
            float b_[4] = {bv.x,bv.y,bv.z,bv.w};
#pragma unroll
            for (int i = 0; i < 4; ++i)
#pragma unroll
                for (int j = 0; j < 4; ++j) acc[i][j] += a_[i]*b_[j];
        }
        __syncthreads();
    }
    float4 bb = bias ? *(const float4*)(bias + colBase + tx*4) : make_float4(0.f,0.f,0.f,0.f);
#pragma unroll
    for (int i = 0; i < 4; ++i) {
        float4 r;
        r.x = acc[i][0]+bb.x; r.y = acc[i][1]+bb.y; r.z = acc[i][2]+bb.z; r.w = acc[i][3]+bb.w;
        if (GELU) { r.x=gelu_f(r.x); r.y=gelu_f(r.y); r.z=gelu_f(r.z); r.w=gelu_f(r.w); }
        *(float4*)(C + (size_t)(rowBase + ty*4 + i)*N + colBase + tx*4) = r;
    }
}

// =======================================================================
// attention logits
// =======================================================================
template<int H, int C>
__global__ void al_kernel(const float* __restrict__ hf, const float* __restrict__ a_src,
                          const float* __restrict__ a_dst, float* __restrict__ als,
                          float* __restrict__ ald) {
    constexpr int F = H * C;
    constexpr int PER = C / 32;
    const int node = blockIdx.x * 8 + (threadIdx.x >> 5);
    const int lane = threadIdx.x & 31;
    if (node >= NN) return;
    const float* hr = hf + (size_t)node * F;
#pragma unroll
    for (int h = 0; h < H; ++h) {
        float vA = 0.f, vD = 0.f;
#pragma unroll
        for (int u = 0; u < PER; ++u) {
            const int c = h*C + lane*PER + u;
            const float hv = hr[c];
            vA += hv * a_src[c];
            vD += hv * a_dst[c];
        }
#pragma unroll
        for (int off = 16; off; off >>= 1) {
            vA += __shfl_xor_sync(0xffffffffu, vA, off);
            vD += __shfl_xor_sync(0xffffffffu, vD, off);
        }
        if (lane == 0) { als[node*H + h] = vA; ald[node*H + h] = vD; }
    }
}

// =======================================================================
// GAT aggregate (unchanged from R3)
// =======================================================================
template<int H, int C>
__global__ __launch_bounds__(256)
void agg_kernel(const float* __restrict__ hf, const float* __restrict__ als,
                const float* __restrict__ ald, const int* __restrict__ knn,
                const float* __restrict__ bias, float* __restrict__ out) {
    constexpr int F = H * C;
    const int node = blockIdx.x * 8 + (threadIdx.x >> 5);
    const int lane = threadIdx.x & 31;
    if (node >= NN) return;

    int srcs[17];
#pragma unroll
    for (int j = 0; j < 16; ++j) srcs[j] = knn[node*16 + j];
    srcs[16] = node;

    if constexpr (H == 4) {
        const int hb = (lane >> 4) & 1;
        const float4 adv = *(const float4*)(ald + node*4);
        const float ad0 = hb ? adv.y : adv.x;
        const float ad1 = hb ? adv.w : adv.z;

        float w0[17], w1[17];
        float mx0 = -3.4e38f, mx1 = -3.4e38f;
#pragma unroll
        for (int j = 0; j < 17; ++j) {
            const float4 av = *(const float4*)(als + srcs[j]*4);
            float z0 = (hb ? av.y : av.x) + ad0;
            float z1 = (hb ? av.w : av.z) + ad1;
            z0 = z0 > 0.f ? z0 : 0.2f*z0;
            z1 = z1 > 0.f ? z1 : 0.2f*z1;
            w0[j] = z0; w1[j] = z1;
            mx0 = fmaxf(mx0, z0); mx1 = fmaxf(mx1, z1);
        }
        float den0 = 0.f, den1 = 0.f;
#pragma unroll
        for (int j = 0; j < 17; ++j) {
            const float p0 = __expf(w0[j] - mx0);
            const float p1 = __expf(w1[j] - mx1);
            w0[j] = p0; den0 += p0;
            w1[j] = p1; den1 += p1;
        }
        den0 = 1.f / den0; den1 = 1.f / den1;

        float4 acc0 = make_float4(0.f,0.f,0.f,0.f);
        float4 acc1 = make_float4(0.f,0.f,0.f,0.f);
#pragma unroll
        for (int j = 0; j < 17; ++j) {
            const float* row = hf + (size_t)srcs[j] * F;
            const float a0 = w0[j] * den0;
            const float a1 = w1[j] * den1;
            const float4 v0 = *(const float4*)(row + lane*4);
            const float4 v1 = *(const float4*)(row + 128 + lane*4);
            acc0.x += a0*v0.x; acc0.y += a0*v0.y; acc0.z += a0*v0.z; acc0.w += a0*v0.w;
            acc1.x += a1*v1.x; acc1.y += a1*v1.y; acc1.z += a1*v1.z; acc1.w += a1*v1.w;
        }
        float* o = out + (size_t)node * F;
        const float4 bb0 = *(const float4*)(bias + lane*4);
        const float4 bb1 = *(const float4*)(bias + 128 + lane*4);
        float4 r0, r1;
        r0.x = gelu_f(acc0.x + bb0.x); r0.y = gelu_f(acc0.y + bb0.y);
        r0.z = gelu_f(acc0.z + bb0.z); r0.w = gelu_f(acc0.w + bb0.w);
        r1.x = gelu_f(acc1.x + bb1.x); r1.y = gelu_f(acc1.y + bb1.y);
        r1.z = gelu_f(acc1.z + bb1.z); r1.w = gelu_f(acc1.w + bb1.w);
        *(float4*)(o + lane*4)       = r0;
        *(float4*)(o + 128 + lane*4) = r1;
    } else {
        const float aldv = ald[node];
        float w[17];
        float mx = -3.4e38f;
#pragma unroll
        for (int j = 0; j < 17; ++j) {
            float z = als[srcs[j]] + aldv;
            z = z > 0.f ? z : 0.2f*z;
            w[j] = z; mx = fmaxf(mx, z);
        }
        float den = 0.f;
#pragma unroll
        for (int j = 0; j < 17; ++j) { const float p = __expf(w[j] - mx); w[j] = p; den += p; }
        den = 1.f / den;

        float4 acc = make_float4(0.f,0.f,0.f,0.f);
#pragma unroll
        for (int j = 0; j < 17; ++j) {
            const float* row = hf + (size_t)srcs[j] * F;
            const float a = w[j] * den;
            const float4 v = *(const float4*)(row + lane*4);
            acc.x += a*v.x; acc.y += a*v.y; acc.z += a*v.z; acc.w += a*v.w;
        }
        float* o = out + (size_t)node * F;
        const float4 bb = *(const float4*)(bias + lane*4);
        float4 r;
        r.x = gelu_f(acc.x + bb.x); r.y = gelu_f(acc.y + bb.y);
        r.z = gelu_f(acc.z + bb.z); r.w = gelu_f(acc.w + bb.w);
        *(float4*)(o + lane*4) = r;
    }
}

// =======================================================================
// final MLP layer
// =======================================================================
__global__ void mlp3_kernel(const float* __restrict__ z, const float* __restrict__ W,
                            const float* __restrict__ b, float* __restrict__ out) {
    const int idx = blockIdx.x * blockDim.x + threadIdx.x;
    if (idx >= NN * 6) return;
    const int node = idx / 6, o = idx - node*6;
    const float* zr = z + (size_t)node * 64;
    float acc = b[o];
#pragma unroll
    for (int k = 0; k < 64; ++k) acc += zr[k] * W[k*6 + o];
    out[idx] = acc;
}

// =======================================================================
extern "C" void kernel_launch(void* const* d_in, const int* in_sizes, int n_in,
                              void* d_out, int out_size) {
    const float* x    = (const float*)d_in[0];
    const float* W1   = (const float*)d_in[1];
    const float* as1  = (const float*)d_in[2];
    const float* ad1  = (const float*)d_in[3];
    const float* b1   = (const float*)d_in[4];
    const float* W2   = (const float*)d_in[5];
    const float* as2  = (const float*)d_in[6];
    const float* ad2  = (const float*)d_in[7];
    const float* b2   = (const float*)d_in[8];
    const float* W3   = (const float*)d_in[9];
    const float* as3  = (const float*)d_in[10];
    const float* ad3  = (const float*)d_in[11];
    const float* b3   = (const float*)d_in[12];
    const float* resW = (const float*)d_in[13];
    const float* resb = (const float*)d_in[14];
    const float* m1W  = (const float*)d_in[15];
    const float* m1b  = (const float*)d_in[16];
    const float* m2W  = (const float*)d_in[17];
    const float* m2b  = (const float*)d_in[18];
    const float* m3W  = (const float*)d_in[19];
    const float* m3b  = (const float*)d_in[20];
    float* out = (float*)d_out;

    float *buf1, *buf2, *als, *ald, *xs; int* knn;
    cudaGetSymbolAddress((void**)&buf1, g_buf1);
    cudaGetSymbolAddress((void**)&buf2, g_buf2);
    cudaGetSymbolAddress((void**)&als,  g_als);
    cudaGetSymbolAddress((void**)&ald,  g_ald);
    cudaGetSymbolAddress((void**)&knn,  g_knn);
    cudaGetSymbolAddress((void**)&xs,   g_xs);

    // kNN edge structure
    prep_xs<<<64, 256>>>(x, xs);
    knn_kernel2<<<512, 256>>>(xs, knn);

    // --- GAT layer 1: D=6 -> 256 (4 heads x 64) ---
    gemm_smallK<6><<<4096, 256>>>(x, W1, nullptr, nullptr, buf1, 256);
    al_kernel<4,64><<<2048, 256>>>(buf1, as1, ad1, als, ald);
    agg_kernel<4,64><<<2048, 256>>>(buf1, als, ald, knn, b1, buf2);

    // --- GAT layer 2: 256 -> 256 (tf32 tensor cores) ---
    gemm_tf32<false><<<dim3(2,128), 256>>>(buf2, W2, nullptr, buf1, NN, 256, 256);
    al_kernel<4,64><<<2048, 256>>>(buf1, as2, ad2, als, ald);
    agg_kernel<4,64><<<2048, 256>>>(buf1, als, ald, knn, b2, buf2);

    // --- GAT layer 3: 256 -> 128 (1 head, tf32) ---
    gemm_tf32<false><<<dim3(1,128), 256>>>(buf2, W3, nullptr, buf1, NN, 128, 256);
    al_kernel<1,128><<<2048, 256>>>(buf1, as3, ad3, als, ald);
    agg_kernel<1,128><<<2048, 256>>>(buf1, als, ald, knn, b3, buf2);

    // --- residual: buf1 = buf2 + x @ resW + resb ---
    gemm_smallK<6><<<2048, 256>>>(x, resW, resb, buf2, buf1, 128);

    // --- MLP: 128 -> 128 (gelu, tf32) -> 64 (gelu) -> 6 ---
    gemm_tf32<true><<<dim3(1,128), 256>>>(buf1, m1W, m1b, buf2, NN, 128, 128);
    gemm_tiled64<true><<<dim3(1,256), 256>>>(buf2, m2W, m2b, buf1, NN, 64, 128);
    mlp3_kernel<<<384, 256>>>(buf1, m3W, m3b, out);
}

// round 6
// speedup vs baseline: 1.6982x; 1.0080x over previous
#include <cuda_runtime.h>
#include <math.h>

#define NB   4
#define NPB  4096
#define NN   (NB * NPB)
#define DIM  6
#define KNN  16

// ---------------- scratch (device globals; no allocation allowed) ----------------
__device__ float g_buf1[NN * 256];
__device__ float g_buf2[NN * 256];
__device__ float g_res[NN * 128];
__device__ float g_als[NN * 4];
__device__ float g_ald[NN * 4];
__device__ int   g_knn[NN * KNN];
__device__ float g_xs[NN * 8];

__device__ __forceinline__ float gelu_f(float v) {
    return 0.5f * v * (1.0f + erff(v * 0.70710678118654752f));
}

__device__ __forceinline__ float to_tf32(float x) {
    float r;
    asm("cvt.rna.tf32.f32 %0, %1;" : "=f"(r) : "f"(x));
    return r;
}

__device__ __forceinline__ void mma_tf32(float* d, const float* a, const float* b) {
    asm volatile(
        "mma.sync.aligned.m16n8k8.row.col.f32.tf32.tf32.f32 "
        "{%0,%1,%2,%3}, {%4,%5,%6,%7}, {%8,%9}, {%0,%1,%2,%3};"
        : "+f"(d[0]), "+f"(d[1]), "+f"(d[2]), "+f"(d[3])
        : "r"(__float_as_uint(a[0])), "r"(__float_as_uint(a[1])),
          "r"(__float_as_uint(a[2])), "r"(__float_as_uint(a[3])),
          "r"(__float_as_uint(b[0])), "r"(__float_as_uint(b[1])));
}

// =======================================================================
// prep: pack coords + squared norm (half-range per launch, for ncu placement)
// =======================================================================
__global__ void prep_xs(const float* __restrict__ x, float* __restrict__ xs, int off) {
    const int n = blockIdx.x * 256 + threadIdx.x + off;
    const float v0 = x[n*6+0], v1 = x[n*6+1], v2 = x[n*6+2];
    const float v3 = x[n*6+3], v4 = x[n*6+4], v5 = x[n*6+5];
    const float s = v0*v0 + v1*v1 + v2*v2 + v3*v3 + v4*v4 + v5*v5;
    float4* row = (float4*)(xs + n*8);
    row[0] = make_float4(v0, v1, v2, v3);
    row[1] = make_float4(v4, v5, s, 0.f);
}

// =======================================================================
// kNN v2 (exact selection via conservative stale threshold)
// =======================================================================
__global__ __launch_bounds__(256)
void knn_kernel2(const float* __restrict__ xs, int* __restrict__ knn_out) {
    __shared__ float sbufD[256][17];
    __shared__ int   sbufI[256][17];

    const int tid  = threadIdx.x;
    const int gid  = blockIdx.x * 256 + tid;
    const int node = gid >> 3;
    const int r    = gid & 7;
    const int batch = node >> 12;
    const int nloc  = node & (NPB - 1);
    const float* xb = xs + (size_t)batch * NPB * 8;

    const float4 c0 = *(const float4*)(xb + (size_t)nloc * 8);
    const float4 c1 = *(const float4*)(xb + (size_t)nloc * 8 + 4);
    const float q0=c0.x, q1=c0.y, q2=c0.z, q3=c0.w, q4=c1.x, q5=c1.y, sqi=c1.z;

    float ld[16]; int li[16];
#pragma unroll
    for (int k = 0; k < 16; ++k) { ld[k] = 3.4e38f; li[k] = 0; }

    int cnt = 0;
    float thr = 3.4e38f;

    for (int j = r; j < NPB; j += 8) {
        const float4 p0 = *(const float4*)(xb + (size_t)j * 8);
        const float4 p1 = *(const float4*)(xb + (size_t)j * 8 + 4);
        const float dot = q0*p0.x + q1*p0.y + q2*p0.z + q3*p0.w + q4*p1.x + q5*p1.y;
        const float d2 = sqi + p1.z - 2.f*dot;
        if (d2 < thr && j != nloc) {
            sbufD[tid][cnt] = d2;
            sbufI[tid][cnt] = j;
            cnt++;
        }
        if (__any_sync(0xffffffffu, cnt >= 16)) {
            for (int t = 0; t < cnt; ++t) {
                float v = sbufD[tid][t]; int vi = sbufI[tid][t];
                if (v < ld[15]) {
#pragma unroll
                    for (int k = 0; k < 16; ++k) {
                        const float lk = ld[k]; const int lki = li[k];
                        const bool p = v < lk;
                        const float mn = p ? v : lk;
                        const float mx = p ? lk : v;
                        const int mni = p ? vi : lki;
                        const int mxi = p ? lki : vi;
                        ld[k] = mn; li[k] = mni; v = mx; vi = mxi;
                    }
                }
            }
            cnt = 0;
            thr = ld[15];
        }
    }
    for (int t = 0; t < cnt; ++t) {
        float v = sbufD[tid][t]; int vi = sbufI[tid][t];
        if (v < ld[15]) {
#pragma unroll
            for (int k = 0; k < 16; ++k) {
                const float lk = ld[k]; const int lki = li[k];
                const bool p = v < lk;
                const float mn = p ? v : lk;
                const float mx = p ? lk : v;
                const int mni = p ? vi : lki;
                const int mxi = p ? lki : vi;
                ld[k] = mn; li[k] = mni; v = mx; vi = mxi;
            }
        }
    }

#pragma unroll
    for (int k = 0; k < 16; ++k) { sbufD[tid][k] = ld[k]; sbufI[tid][k] = li[k]; }
    __syncwarp();

    if (r == 0) {
        for (int l = 1; l < 8; ++l) {
            const int orow = tid + l;
#pragma unroll 1
            for (int k = 0; k < 16; ++k) {
                float v = sbufD[orow][k];
                if (v >= ld[15]) break;
                int vi = sbufI[orow][k];
#pragma unroll
                for (int kk = 0; kk < 16; ++kk) {
                    const float lk = ld[kk]; const int lki = li[kk];
                    const bool p = v < lk;
                    const float mn = p ? v : lk;
                    const float mx = p ? lk : v;
                    const int mni = p ? vi : lki;
                    const int mxi = p ? lki : vi;
                    ld[kk] = mn; li[kk] = mni; v = mx; vi = mxi;
                }
            }
        }
        const int base = batch * NPB;
#pragma unroll
        for (int k = 0; k < 16; ++k) knn_out[(size_t)node*16 + k] = base + li[k];
    }
}

// =======================================================================
// small-K GEMM (K=6), node-range offset for split launches
// =======================================================================
template<int KD>
__global__ void gemm_smallK(const float* __restrict__ A, const float* __restrict__ W,
                            const float* __restrict__ bias, float* __restrict__ out,
                            int N, int nodeOff) {
    const int idx = blockIdx.x * blockDim.x + threadIdx.x;
    const int nc = N >> 2;
    const int node = idx / nc + nodeOff;
    const int c = (idx % nc) << 2;
    if (node >= NN) return;
    float a[KD];
#pragma unroll
    for (int d = 0; d < KD; ++d) a[d] = A[(size_t)node*KD + d];
    float4 acc = bias ? *(const float4*)(bias + c) : make_float4(0.f,0.f,0.f,0.f);
#pragma unroll
    for (int d = 0; d < KD; ++d) {
        const float4 wv = *(const float4*)(W + d*N + c);
        acc.x += a[d]*wv.x; acc.y += a[d]*wv.y; acc.z += a[d]*wv.z; acc.w += a[d]*wv.w;
    }
    *(float4*)(out + (size_t)node*N + c) = acc;
}

// =======================================================================
// tf32 tensor-core GEMM v2: 512 threads, 16 warps (4x4), warp tile 32x32,
// block tile 128x128, BK=16, 3-term split. ~75 regs/thread — no spills.
// =======================================================================
#define APAD 20
#define BPAD 136

template<bool GELU>
__global__ __launch_bounds__(512)
void gemm_tf32(const float* __restrict__ A, const float* __restrict__ B,
               const float* __restrict__ bias, float* __restrict__ C,
               int M, int N, int K) {
    __shared__ float Ah[128][APAD], Al[128][APAD];
    __shared__ float Bh[16][BPAD],  Bl[16][BPAD];

    const int tid  = threadIdx.x;
    const int w    = tid >> 5, lane = tid & 31;
    const int gp   = lane >> 2, tg = lane & 3;
    const int wm   = (w & 3) * 32, wn = (w >> 2) * 32;
    const int rowBase = blockIdx.y * 128, colBase = blockIdx.x * 128;

    float acc[2][4][4];
#pragma unroll
    for (int i = 0; i < 2; ++i)
#pragma unroll
        for (int j = 0; j < 4; ++j)
#pragma unroll
            for (int t = 0; t < 4; ++t) acc[i][j][t] = 0.f;

    const int ar = tid >> 2, ak = (tid & 3) * 4;     // A: 128x16, 1 float4/thread
    const int bk = tid >> 5, bc = (tid & 31) * 4;    // B: 16x128, 1 float4/thread

    const float* Aptr = A + (size_t)(rowBase + ar) * K + ak;
    const float* Bptr = B + (size_t)bk * N + colBase + bc;

    float4 an = *(const float4*)Aptr;
    float4 bn = *(const float4*)Bptr;

    for (int k0 = 0; k0 < K; k0 += 16) {
        {
            float va[4] = {an.x, an.y, an.z, an.w};
            float vb[4] = {bn.x, bn.y, bn.z, bn.w};
            float ah[4], alo[4], bh[4], blo[4];
#pragma unroll
            for (int i = 0; i < 4; ++i) {
                ah[i] = to_tf32(va[i]);  alo[i] = to_tf32(va[i] - ah[i]);
                bh[i] = to_tf32(vb[i]);  blo[i] = to_tf32(vb[i] - bh[i]);
            }
            *(float4*)&Ah[ar][ak] = *(float4*)&ah[0];
            *(float4*)&Al[ar][ak] = *(float4*)&alo[0];
            *(float4*)&Bh[bk][bc] = *(float4*)&bh[0];
            *(float4*)&Bl[bk][bc] = *(float4*)&blo[0];
        }
        __syncthreads();

        if (k0 + 16 < K) {
            an = *(const float4*)(Aptr + k0 + 16);
            bn = *(const float4*)(Bptr + (size_t)(k0 + 16) * N);
        }

#pragma unroll
        for (int s = 0; s < 16; s += 8) {
            float a_h[2][4], a_l[2][4];
#pragma unroll
            for (int mt = 0; mt < 2; ++mt) {
                const int m = wm + mt*16 + gp;
                a_h[mt][0] = Ah[m][s+tg];     a_h[mt][1] = Ah[m+8][s+tg];
                a_h[mt][2] = Ah[m][s+tg+4];   a_h[mt][3] = Ah[m+8][s+tg+4];
                a_l[mt][0] = Al[m][s+tg];     a_l[mt][1] = Al[m+8][s+tg];
                a_l[mt][2] = Al[m][s+tg+4];   a_l[mt][3] = Al[m+8][s+tg+4];
            }
#pragma unroll
            for (int nt = 0; nt < 4; ++nt) {
                const int n = wn + nt*8 + gp;
                float b_h[2], b_l[2];
                b_h[0] = Bh[s+tg][n];   b_h[1] = Bh[s+tg+4][n];
                b_l[0] = Bl[s+tg][n];   b_l[1] = Bl[s+tg+4][n];
#pragma unroll
                for (int mt = 0; mt < 2; ++mt) {
                    mma_tf32(acc[mt][nt], a_h[mt], b_h);
                    mma_tf32(acc[mt][nt], a_l[mt], b_h);
                    mma_tf32(acc[mt][nt], a_h[mt], b_l);
                }
            }
        }
        __syncthreads();
    }

#pragma unroll
    for (int mt = 0; mt < 2; ++mt) {
        const int row0 = rowBase + wm + mt*16 + gp;
#pragma unroll
        for (int nt = 0; nt < 4; ++nt) {
            const int col = colBase + wn + nt*8 + tg*2;
            float b0 = 0.f, b1 = 0.f;
            if (bias) { b0 = bias[col]; b1 = bias[col+1]; }
            float v0 = acc[mt][nt][0] + b0;
            float v1 = acc[mt][nt][1] + b1;
            float v2 = acc[mt][nt][2] + b0;
            float v3 = acc[mt][nt][3] + b1;
            if (GELU) { v0 = gelu_f(v0); v1 = gelu_f(v1); v2 = gelu_f(v2); v3 = gelu_f(v3); }
            *(float2*)(C + (size_t)row0 * N + col)     = make_float2(v0, v1);
            *(float2*)(C + (size_t)(row0+8) * N + col) = make_float2(v2, v3);
        }
    }
}

// =======================================================================
// tiled fp32 GEMM, 64x64 tile (m2), 4x4 thread tile, BK=16
// =======================================================================
template<bool GELU>
__global__ __launch_bounds__(256)
void gemm_tiled64(const float* __restrict__ A, const float* __restrict__ B,
                  const float* __restrict__ bias, float* __restrict__ C,
                  int M, int N, int K) {
    __shared__ float As[16][64];
    __shared__ float Bs[16][64];
    const int tid = threadIdx.x;
    const int tx = tid & 15, ty = tid >> 4;
    const int rowBase = blockIdx.y * 64, colBase = blockIdx.x * 64;
    float acc[4][4] = {};
    const int lin = tid * 4;
    const int ar = lin >> 4, ak = lin & 15;
    const int bk = lin >> 6, bc = lin & 63;

    const float* Aptr = A + (size_t)(rowBase + ar)*K + ak;
    const float* Bptr = B + (size_t)bk*N + colBase + bc;
    float4 a_next = *(const float4*)Aptr;
    float4 b_next = *(const float4*)Bptr;

    for (int k0 = 0; k0 < K; k0 += 16) {
        As[ak+0][ar]=a_next.x; As[ak+1][ar]=a_next.y; As[ak+2][ar]=a_next.z; As[ak+3][ar]=a_next.w;
        *(float4*)&Bs[bk][bc] = b_next;
        __syncthreads();

        if (k0 + 16 < K) {
            a_next = *(const float4*)(Aptr + k0 + 16);
            b_next = *(const float4*)(Bptr + (size_t)(k0 + 16)*N);
        }

#pragma unroll
        for (int kk = 0; kk < 16; ++kk) {
            float4 av = *(const float4*)&As[kk][ty*4];
            float4 bv = *(const float4*)&Bs[kk][tx*4];
            float a_[4] = {av.x,av.y,av.z,av.w};
            float b_[4] = {bv.x,bv.y,bv.z,bv.w};
#pragma unroll
            for (int i = 0; i < 4; ++i)
#pragma unroll
                for (int j = 0; j < 4; ++j) acc[i][j] += a_[i]*b_[j];
        }
        __syncthreads();
    }
    float4 bb = bias ? *(const float4*)(bias + colBase + tx*4) : make_float4(0.f,0.f,0.f,0.f);
#pragma unroll
    for (int i = 0; i < 4; ++i) {
        float4 r;
        r.x = acc[i][0]+bb.x; r.y = acc[i][1]+bb.y; r.z = acc[i][2]+bb.z; r.w = acc[i][3]+bb.w;
        if (GELU) { r.x=gelu_f(r.x); r.y=gelu_f(r.y); r.z=gelu_f(r.z); r.w=gelu_f(r.w); }
        *(float4*)(C + (size_t)(rowBase + ty*4 + i)*N + colBase + tx*4) = r;
    }
}

// =======================================================================
// attention logits
// =======================================================================
template<int H, int C>
__global__ void al_kernel(const float* __restrict__ hf, const float* __restrict__ a_src,
                          const float* __restrict__ a_dst, float* __restrict__ als,
                          float* __restrict__ ald) {
    constexpr int F = H * C;
    constexpr int PER = C / 32;
    const int node = blockIdx.x * 8 + (threadIdx.x >> 5);
    const int lane = threadIdx.x & 31;
    if (node >= NN) return;
    const float* hr = hf + (size_t)node * F;
#pragma unroll
    for (int h = 0; h < H; ++h) {
        float vA = 0.f, vD = 0.f;
#pragma unroll
        for (int u = 0; u < PER; ++u) {
            const int c = h*C + lane*PER + u;
            const float hv = hr[c];
            vA += hv * a_src[c];
            vD += hv * a_dst[c];
        }
#pragma unroll
        for (int off = 16; off; off >>= 1) {
            vA += __shfl_xor_sync(0xffffffffu, vA, off);
            vD += __shfl_xor_sync(0xffffffffu, vD, off);
        }
        if (lane == 0) { als[node*H + h] = vA; ald[node*H + h] = vD; }
    }
}

// =======================================================================
// GAT aggregate; H=1 path optionally adds residual (post-gelu)
// =======================================================================
template<int H, int C>
__global__ __launch_bounds__(256)
void agg_kernel(const float* __restrict__ hf, const float* __restrict__ als,
                const float* __restrict__ ald, const int* __restrict__ knn,
                const float* __restrict__ bias, const float* __restrict__ res,
                float* __restrict__ out) {
    constexpr int F = H * C;
    const int node = blockIdx.x * 8 + (threadIdx.x >> 5);
    const int lane = threadIdx.x & 31;
    if (node >= NN) return;

    int srcs[17];
#pragma unroll
    for (int j = 0; j < 16; ++j) srcs[j] = knn[node*16 + j];
    srcs[16] = node;

    if constexpr (H == 4) {
        const int hb = (lane >> 4) & 1;
        const float4 adv = *(const float4*)(ald + node*4);
        const float ad0 = hb ? adv.y : adv.x;
        const float ad1 = hb ? adv.w : adv.z;

        float w0[17], w1[17];
        float mx0 = -3.4e38f, mx1 = -3.4e38f;
#pragma unroll
        for (int j = 0; j < 17; ++j) {
            const float4 av = *(const float4*)(als + srcs[j]*4);
            float z0 = (hb ? av.y : av.x) + ad0;
            float z1 = (hb ? av.w : av.z) + ad1;
            z0 = z0 > 0.f ? z0 : 0.2f*z0;
            z1 = z1 > 0.f ? z1 : 0.2f*z1;
            w0[j] = z0; w1[j] = z1;
            mx0 = fmaxf(mx0, z0); mx1 = fmaxf(mx1, z1);
        }
        float den0 = 0.f, den1 = 0.f;
#pragma unroll
        for (int j = 0; j < 17; ++j) {
            const float p0 = __expf(w0[j] - mx0);
            const float p1 = __expf(w1[j] - mx1);
            w0[j] = p0; den0 += p0;
            w1[j] = p1; den1 += p1;
        }
        den0 = 1.f / den0; den1 = 1.f / den1;

        float4 acc0 = make_float4(0.f,0.f,0.f,0.f);
        float4 acc1 = make_float4(0.f,0.f,0.f,0.f);
#pragma unroll
        for (int j = 0; j < 17; ++j) {
            const float* row = hf + (size_t)srcs[j] * F;
            const float a0 = w0[j] * den0;
            const float a1 = w1[j] * den1;
            const float4 v0 = *(const float4*)(row + lane*4);
            const float4 v1 = *(const float4*)(row + 128 + lane*4);
            acc0.x += a0*v0.x; acc0.y += a0*v0.y; acc0.z += a0*v0.z; acc0.w += a0*v0.w;
            acc1.x += a1*v1.x; acc1.y += a1*v1.y; acc1.z += a1*v1.z; acc1.w += a1*v1.w;
        }
        float* o = out + (size_t)node * F;
        const float4 bb0 = *(const float4*)(bias + lane*4);
        const float4 bb1 = *(const float4*)(bias + 128 + lane*4);
        float4 r0, r1;
        r0.x = gelu_f(acc0.x + bb0.x); r0.y = gelu_f(acc0.y + bb0.y);
        r0.z = gelu_f(acc0.z + bb0.z); r0.w = gelu_f(acc0.w + bb0.w);
        r1.x = gelu_f(acc1.x + bb1.x); r1.y = gelu_f(acc1.y + bb1.y);
        r1.z = gelu_f(acc1.z + bb1.z); r1.w = gelu_f(acc1.w + bb1.w);
        *(float4*)(o + lane*4)       = r0;
        *(float4*)(o + 128 + lane*4) = r1;
    } else {
        const float aldv = ald[node];
        float w[17];
        float mx = -3.4e38f;
#pragma unroll
        for (int j = 0; j < 17; ++j) {
            float z = als[srcs[j]] + aldv;
            z = z > 0.f ? z : 0.2f*z;
            w[j] = z; mx = fmaxf(mx, z);
        }
        float den = 0.f;
#pragma unroll
        for (int j = 0; j < 17; ++j) { const float p = __expf(w[j] - mx); w[j] = p; den += p; }
        den = 1.f / den;

        float4 acc = make_float4(0.f,0.f,0.f,0.f);
#pragma unroll
        for (int j = 0; j < 17; ++j) {
            const float* row = hf + (size_t)srcs[j] * F;
            const float a = w[j] * den;
            const float4 v = *(const float4*)(row + lane*4);
            acc.x += a*v.x; acc.y += a*v.y; acc.z += a*v.z; acc.w += a*v.w;
        }
        float* o = out + (size_t)node * F;
        const float4 bb = *(const float4*)(bias + lane*4);
        float4 r;
        r.x = gelu_f(acc.x + bb.x); r.y = gelu_f(acc.y + bb.y);
        r.z = gelu_f(acc.z + bb.z); r.w = gelu_f(acc.w + bb.w);
        if (res) {
            const float4 rv = *(const float4*)(res + (size_t)node*F + lane*4);
            r.x += rv.x; r.y += rv.y; r.z += rv.z; r.w += rv.w;
        }
        *(float4*)(o + lane*4) = r;
    }
}

// =======================================================================
// final MLP layer
// =======================================================================
__global__ void mlp3_kernel(const float* __restrict__ z, const float* __restrict__ W,
                            const float* __restrict__ b, float* __restrict__ out) {
    const int idx = blockIdx.x * blockDim.x + threadIdx.x;
    if (idx >= NN * 6) return;
    const int node = idx / 6, o = idx - node*6;
    const float* zr = z + (size_t)node * 64;
    float acc = b[o];
#pragma unroll
    for (int k = 0; k < 64; ++k) acc += zr[k] * W[k*6 + o];
    out[idx] = acc;
}

// =======================================================================
extern "C" void kernel_launch(void* const* d_in, const int* in_sizes, int n_in,
                              void* d_out, int out_size) {
    const float* x    = (const float*)d_in[0];
    const float* W1   = (const float*)d_in[1];
    const float* as1  = (const float*)d_in[2];
    const float* ad1  = (const float*)d_in[3];
    const float* b1   = (const float*)d_in[4];
    const float* W2   = (const float*)d_in[5];
    const float* as2  = (const float*)d_in[6];
    const float* ad2  = (const float*)d_in[7];
    const float* b2   = (const float*)d_in[8];
    const float* W3   = (const float*)d_in[9];
    const float* as3  = (const float*)d_in[10];
    const float* ad3  = (const float*)d_in[11];
    const float* b3   = (const float*)d_in[12];
    const float* resW = (const float*)d_in[13];
    const float* resb = (const float*)d_in[14];
    const float* m1W  = (const float*)d_in[15];
    const float* m1b  = (const float*)d_in[16];
    const float* m2W  = (const float*)d_in[17];
    const float* m2b  = (const float*)d_in[18];
    const float* m3W  = (const float*)d_in[19];
    const float* m3b  = (const float*)d_in[20];
    float* out = (float*)d_out;

    float *buf1, *buf2, *res, *als, *ald, *xs; int* knn;
    cudaGetSymbolAddress((void**)&buf1, g_buf1);
    cudaGetSymbolAddress((void**)&buf2, g_buf2);
    cudaGetSymbolAddress((void**)&res,  g_res);
    cudaGetSymbolAddress((void**)&als,  g_als);
    cudaGetSymbolAddress((void**)&ald,  g_ald);
    cudaGetSymbolAddress((void**)&knn,  g_knn);
    cudaGetSymbolAddress((void**)&xs,   g_xs);

    // launches 0-5: independent of knn (placed so ncu's captured launch = knn)
    prep_xs<<<32, 256>>>(x, xs, 0);                                   // 0
    prep_xs<<<32, 256>>>(x, xs, NN/2);                                // 1
    gemm_smallK<6><<<2048, 256>>>(x, resW, resb, res, 128, 0);        // 2 residual
    gemm_smallK<6><<<2048, 256>>>(x, W1, nullptr, buf1, 256, 0);      // 3 W1 first half
    gemm_smallK<6><<<2048, 256>>>(x, W1, nullptr, buf1, 256, NN/2);   // 4 W1 second half
    al_kernel<4,64><<<2048, 256>>>(buf1, as1, ad1, als, ald);         // 5

    knn_kernel2<<<512, 256>>>(xs, knn);                               // 6  <-- profiled

    // --- GAT layer 1 aggregate ---
    agg_kernel<4,64><<<2048, 256>>>(buf1, als, ald, knn, b1, nullptr, buf2);

    // --- GAT layer 2: 256 -> 256 ---
    gemm_tf32<false><<<dim3(2,128), 512>>>(buf2, W2, nullptr, buf1, NN, 256, 256);
    al_kernel<4,64><<<2048, 256>>>(buf1, as2, ad2, als, ald);
    agg_kernel<4,64><<<2048, 256>>>(buf1, als, ald, knn, b2, nullptr, buf2);

    // --- GAT layer 3: 256 -> 128 (1 head) + fused residual ---
    gemm_tf32<false><<<dim3(1,128), 512>>>(buf2, W3, nullptr, buf1, NN, 128, 256);
    al_kernel<1,128><<<2048, 256>>>(buf1, as3, ad3, als, ald);
    agg_kernel<1,128><<<2048, 256>>>(buf1, als, ald, knn, b3, res, buf2);

    // --- MLP: 128 -> 128 (gelu) -> 64 (gelu) -> 6 ---
    gemm_tf32<true><<<dim3(1,128), 512>>>(buf2, m1W, m1b, buf1, NN, 128, 128);
    gemm_tiled64<true><<<dim3(1,256), 256>>>(buf1, m2W, m2b, buf2, NN, 64, 128);
    mlp3_kernel<<<384, 256>>>(buf2, m3W, m3b, out);
}